// round 7
// baseline (speedup 1.0000x reference)
#include <cuda_runtime.h>
#include <cstdint>

// Conv4D with separable rank-1 kernel (K ⊗ K), VALID padding.
// input  : (8192, 8, 8, 8, 8) fp32 -> output (8192, 6, 6, 6, 6) fp32
//
// One CTA per batch, 192 threads (6 warps), 6 CTAs/SM (reg-capped 56):
//   stage : gmem -> smem, coalesced scalar LDG(.cs) + conflict-free STS (65-pad)
//   pass1 : conv over (d3,d4); 192 units (third, ab), lanes along ab
//           (65 == 1 mod 32 -> conflict-free), rolling 3-row window, 2 e3/unit
//   pass2 : conv over (d1,d2) from 37-padded T planes; lanes along e34
//           (conflict-free LDS, coalesced STG(.cs))

#define THREADS 192

__global__ __launch_bounds__(THREADS, 6)
void conv4d_sep4_kernel(const float* __restrict__ in,
                        const float* __restrict__ ker,
                        float* __restrict__ out)
{
    __shared__ float s_in[64 * 65];   // input planes, padded: 16,640 B
    __shared__ float s_t [64 * 37];   // T planes, padded:      9,472 B

    const int b   = blockIdx.x;
    const int tid = threadIdx.x;

    float k[9];
#pragma unroll
    for (int i = 0; i < 9; i++) k[i] = __ldg(&ker[i]);

    const float* gin = in + (size_t)b * 4096;

    // ---- Stage: 4096 floats. tid -> (plane p0 = tid/64, word w = tid%64),
    // advancing 3 planes per step (192 threads = 3 planes). Lanes along w:
    // coalesced LDG, conflict-free STS.
    {
        const int w  = tid & 63;
        int       p  = tid >> 6;          // 0..2
        const float* g = gin + p * 64 + w;
        float*       s = s_in + p * 65 + w;
        for (; p < 64; p += 3) {
            *s = __ldcs(g);
            g += 3 * 64;
            s += 3 * 65;
        }
    }
    __syncthreads();

    // ---- Pass 1: correlate (d3,d4). Unit = (third, ab): e3 in {2t, 2t+1},
    // reads rows 2t..2t+3. Lanes along ab -> conflict-free (65 % 32 == 1).
    {
        const int t  = tid / 64;          // 0..2
        const int ab = tid & 63;
        const float* sp = &s_in[ab * 65 + t * 16];   // rows 2t ..
        float*       tp = &s_t [ab * 37 + t * 12];

        float r[3][8];
#pragma unroll
        for (int c = 0; c < 8; c++) { r[0][c] = sp[c]; r[1][c] = sp[8 + c]; }

#pragma unroll
        for (int e3 = 0; e3 < 2; e3++) {
#pragma unroll
            for (int c = 0; c < 8; c++)
                r[(e3 + 2) % 3][c] = sp[(e3 + 2) * 8 + c];

            float acc[6];
#pragma unroll
            for (int e4 = 0; e4 < 6; e4++) acc[e4] = 0.0f;
#pragma unroll
            for (int kk = 0; kk < 3; kk++) {
                const float* row = r[(e3 + kk) % 3];
#pragma unroll
                for (int ll = 0; ll < 3; ll++) {
                    const float kv = k[kk * 3 + ll];
#pragma unroll
                    for (int e4 = 0; e4 < 6; e4++)
                        acc[e4] = fmaf(row[e4 + ll], kv, acc[e4]);
                }
            }
#pragma unroll
            for (int e4 = 0; e4 < 6; e4++) tp[e3 * 6 + e4] = acc[e4];
        }
    }
    __syncthreads();

    // ---- Pass 2: correlate (d1,d2). Unit v = (e1, e34), lanes along e34:
    // conflict-free LDS, contiguous coalesced streaming stores.
    float* gout = out + (size_t)b * 1296;
#pragma unroll
    for (int p = 0; p < 2; p++) {
        const int v = tid + p * THREADS;        // 0..383; active if < 216
        if (v < 216) {
            const int e1  = v / 36;
            const int e34 = v - e1 * 36;

            float t[3][8];
#pragma unroll
            for (int i = 0; i < 3; i++)
#pragma unroll
                for (int j = 0; j < 8; j++)
                    t[i][j] = s_t[((e1 + i) * 8 + j) * 37 + e34];

            float acc[6];
#pragma unroll
            for (int e2 = 0; e2 < 6; e2++) acc[e2] = 0.0f;
#pragma unroll
            for (int i = 0; i < 3; i++)
#pragma unroll
                for (int j = 0; j < 3; j++) {
                    const float kv = k[i * 3 + j];
#pragma unroll
                    for (int e2 = 0; e2 < 6; e2++)
                        acc[e2] = fmaf(t[i][e2 + j], kv, acc[e2]);
                }

#pragma unroll
            for (int e2 = 0; e2 < 6; e2++)
                __stcs(&gout[e1 * 216 + e2 * 36 + e34], acc[e2]);
        }
    }
}

extern "C" void kernel_launch(void* const* d_in, const int* in_sizes, int n_in,
                              void* d_out, int out_size)
{
    const float* in  = (const float*)d_in[0];   // (8192,8,8,8,8) fp32
    const float* ker = (const float*)d_in[1];   // (3,3) fp32
    float*       out = (float*)d_out;           // (8192,6,6,6,6) fp32

    const int batches = in_sizes[0] / 4096;     // 8192
    conv4d_sep4_kernel<<<batches, THREADS>>>(in, ker, out);
}

// round 8
// speedup vs baseline: 1.5697x; 1.5697x over previous
#include <cuda_runtime.h>
#include <cstdint>

// Conv4D with separable rank-1 kernel (K ⊗ K), VALID padding.
// input  : (8192, 8, 8, 8, 8) fp32 -> output (8192, 6, 6, 6, 6) fp32
//
// One CTA per batch, 128 threads, 10 CTAs/SM (17.8 KB smem, 51-reg cap):
//   stage : input staged in 2 chunks of 32 planes through one 8.3 KB buffer
//           (fully-unrolled 16x LDG per chunk -> high MLP, conflict-free STS)
//   pass1 : per chunk, 128 units (plane, e3-half, e4-half), 5x5 register
//           window -> 3x3 outputs; lanes along plane (65 = 1 mod 32, CF)
//   pass2 : 144 units (u, h, e34), 5x5 window over T -> 3x3 outputs;
//           lanes along e34 (CF), coalesced stores

#define THREADS 128

__global__ __launch_bounds__(THREADS, 10)
void conv4d_sep5_kernel(const float* __restrict__ in,
                        const float* __restrict__ ker,
                        float* __restrict__ out)
{
    __shared__ float s_in[32 * 65];   // one 32-plane chunk, padded: 8,320 B
    __shared__ float s_t [64 * 37];   // T planes, padded:            9,472 B

    const int b   = blockIdx.x;
    const int tid = threadIdx.x;

    float k[9];
#pragma unroll
    for (int i = 0; i < 9; i++) k[i] = __ldg(&ker[i]);

    const float* gin = in + (size_t)b * 4096;

    const int w  = tid & 63;          // word within plane (stage)
    const int p0 = tid >> 6;          // 0..1              (stage)

    const int pl  = tid & 31;         // pass1 plane within chunk
    const int e3h = (tid >> 5) & 1;   // pass1 e3 half
    const int e4h = tid >> 6;         // pass1 e4 half

#pragma unroll
    for (int chunk = 0; chunk < 2; chunk++) {
        if (chunk) __syncthreads();   // pass1 of prev chunk done before reuse

        // ---- Stage chunk: 32 planes, fully unrolled (MLP ~16), coalesced LDG,
        // conflict-free STS (65-pad, lanes along w).
        {
            const float* g = gin + chunk * 32 * 64;
#pragma unroll
            for (int i = 0; i < 16; i++) {
                const int plane = p0 + 2 * i;
                s_in[plane * 65 + w] = __ldg(g + plane * 64 + w);
            }
        }
        __syncthreads();

        // ---- Pass 1 on chunk: unit = (pl, e3h, e4h) computes 3x3 outputs.
        // Reads rows 3*e3h..3*e3h+4, cols 3*e4h..3*e4h+4 (5x5, rolling 3 rows).
        // Lanes along pl -> bank = (pl + c) mod 32, conflict-free.
        {
            const float* sp = &s_in[pl * 65 + e3h * 24 + e4h * 3];
            float*       tp = &s_t[(chunk * 32 + pl) * 37 + e3h * 18 + e4h * 3];

            float r[3][5];
#pragma unroll
            for (int c = 0; c < 5; c++) { r[0][c] = sp[c]; r[1][c] = sp[8 + c]; }

#pragma unroll
            for (int e3 = 0; e3 < 3; e3++) {
#pragma unroll
                for (int c = 0; c < 5; c++)
                    r[(e3 + 2) % 3][c] = sp[(e3 + 2) * 8 + c];

                float acc[3];
#pragma unroll
                for (int e4 = 0; e4 < 3; e4++) acc[e4] = 0.0f;
#pragma unroll
                for (int kk = 0; kk < 3; kk++) {
                    const float* row = r[(e3 + kk) % 3];
#pragma unroll
                    for (int ll = 0; ll < 3; ll++) {
                        const float kv = k[kk * 3 + ll];
#pragma unroll
                        for (int e4 = 0; e4 < 3; e4++)
                            acc[e4] = fmaf(row[e4 + ll], kv, acc[e4]);
                    }
                }
#pragma unroll
                for (int e4 = 0; e4 < 3; e4++) tp[e3 * 6 + e4] = acc[e4];
            }
        }
    }
    __syncthreads();

    // ---- Pass 2: 144 units (u, h, e34): e1 in {3u..3u+2}, e2 in {3h..3h+2}.
    // Reads T rows (d1) 3u..3u+4, cols (d2) 3h..3h+4 (5x5, rolling 3 rows);
    // lanes along e34 -> conflict-free LDS, coalesced stores.
    float* gout = out + (size_t)b * 1296;
#pragma unroll
    for (int base = 0; base < 144; base += THREADS) {
        const int v = tid + base;
        if (v < 144) {
            const int q   = v / 36;          // 0..3
            const int u   = q >> 1;          // e1 group
            const int h   = q & 1;           // e2 group
            const int e34 = v - q * 36;

            const float* tb = &s_t[(u * 3 * 8 + h * 3) * 37 + e34];

            float r[3][5];
#pragma unroll
            for (int j = 0; j < 5; j++) {
                r[0][j] = tb[(0 * 8 + j) * 37];
                r[1][j] = tb[(1 * 8 + j) * 37];
            }

#pragma unroll
            for (int e1l = 0; e1l < 3; e1l++) {
#pragma unroll
                for (int j = 0; j < 5; j++)
                    r[(e1l + 2) % 3][j] = tb[((e1l + 2) * 8 + j) * 37];

                float acc[3];
#pragma unroll
                for (int e2 = 0; e2 < 3; e2++) acc[e2] = 0.0f;
#pragma unroll
                for (int i = 0; i < 3; i++) {
                    const float* row = r[(e1l + i) % 3];
#pragma unroll
                    for (int j = 0; j < 3; j++) {
                        const float kv = k[i * 3 + j];
#pragma unroll
                        for (int e2 = 0; e2 < 3; e2++)
                            acc[e2] = fmaf(row[e2 + j], kv, acc[e2]);
                    }
                }

                const int e1 = u * 3 + e1l;
#pragma unroll
                for (int e2 = 0; e2 < 3; e2++)
                    gout[e1 * 216 + (h * 3 + e2) * 36 + e34] = acc[e2];
            }
        }
    }
}

extern "C" void kernel_launch(void* const* d_in, const int* in_sizes, int n_in,
                              void* d_out, int out_size)
{
    const float* in  = (const float*)d_in[0];   // (8192,8,8,8,8) fp32
    const float* ker = (const float*)d_in[1];   // (3,3) fp32
    float*       out = (float*)d_out;           // (8192,6,6,6,6) fp32

    const int batches = in_sizes[0] / 4096;     // 8192
    conv4d_sep5_kernel<<<batches, THREADS>>>(in, ker, out);
}

// round 9
// speedup vs baseline: 1.7484x; 1.1139x over previous
#include <cuda_runtime.h>
#include <cstdint>

// Conv4D with separable rank-1 kernel (K ⊗ K), VALID padding.
// input  : (8192, 8, 8, 8, 8) fp32 -> output (8192, 6, 6, 6, 6) fp32
//
// Pass 1 computed straight from coalesced LDG.128 registers using warp
// shuffles (no input staging in smem):
//   lane L, warp w, instr j  ->  plane 16w+2j+(L>>4), row (L>>1)&7, colhalf L&1
//   d4 conv: 1 shfl.bfly(1) borrow -> 5-col window -> rp[3][3]
//   d3 conv: rows rr+1, rr+2 via shfl.down 2 / 4
// T stored in smem with plane stride 48 (== 16 mod 32): store banks
// 16*hi + 6*rr + 3c all distinct -> conflict-free; pass-2 reads lanes along
// e34 (stride 1) -> conflict-free; coalesced output stores.

#define THREADS 128
#define FULLM 0xffffffffu

__global__ __launch_bounds__(THREADS, 8)
void conv4d_shfl_kernel(const float* __restrict__ in,
                        const float* __restrict__ ker,
                        float* __restrict__ out)
{
    __shared__ float s_t[64 * 48];   // T[plane][e34], stride 48: 12,288 B

    const int b   = blockIdx.x;
    const int tid = threadIdx.x;
    const int w   = tid >> 5;        // warp 0..3
    const int L   = tid & 31;        // lane

    const int hi = L >> 4;           // plane parity within pair
    const int rr = (L >> 1) & 7;     // input row 0..7
    const int c  = L & 1;            // col half 0..1

    float k[9];
#pragma unroll
    for (int i = 0; i < 9; i++) k[i] = __ldg(&ker[i]);

    const float4* gin4 = reinterpret_cast<const float4*>(in + (size_t)b * 4096);

    // ---- 8 fully-coalesced LDG.128 (4 lines per warp-op, MLP=8) ----
    float4 q[8];
#pragma unroll
    for (int j = 0; j < 8; j++)
        q[j] = __ldg(gin4 + w * 256 + j * 32 + L);

    const int plane_base = w * 16 + hi;          // plane = plane_base + 2j

    // ---- Pass 1: per plane j, conv (d3,d4) via shuffles ----
#pragma unroll
    for (int j = 0; j < 8; j++) {
        const float x0 = q[j].x, x1 = q[j].y, x2 = q[j].z, x3 = q[j].w;

        // borrow 1 float from the other col-half (col 4 for c=0, col 3 for c=1)
        const float sendv = c ? x0 : x3;
        const float recv  = __shfl_xor_sync(FULLM, sendv, 1);

        // 5-col window: cols 3c .. 3c+4
        float win[5];
        win[0] = c ? recv : x0;
        win[1] = c ? x0   : x1;
        win[2] = c ? x1   : x2;
        win[3] = c ? x2   : x3;
        win[4] = c ? x3   : recv;

        // row partials rp[kk][m]: e4 = 3c+m, kernel row kk
        float rp[3][3];
#pragma unroll
        for (int kk = 0; kk < 3; kk++)
#pragma unroll
            for (int m = 0; m < 3; m++)
                rp[kk][m] = fmaf(win[m],     k[kk * 3 + 0],
                            fmaf(win[m + 1], k[kk * 3 + 1],
                                 win[m + 2] * k[kk * 3 + 2]));

        // rows rr+1 (lane +2) and rr+2 (lane +4)
        float r1[3], r2[3];
#pragma unroll
        for (int m = 0; m < 3; m++) r1[m] = __shfl_down_sync(FULLM, rp[1][m], 2);
#pragma unroll
        for (int m = 0; m < 3; m++) r2[m] = __shfl_down_sync(FULLM, rp[2][m], 4);

        if (rr < 6) {
            const int plane = plane_base + 2 * j;
            float* tp = &s_t[plane * 48 + rr * 6 + c * 3];
            tp[0] = rp[0][0] + r1[0] + r2[0];
            tp[1] = rp[0][1] + r1[1] + r2[1];
            tp[2] = rp[0][2] + r1[2] + r2[2];
        }
    }
    __syncthreads();

    // ---- Pass 2: conv over (d1,d2). 144 units (u, h, e34), 5x5 rolling
    // window; lanes along e34 -> conflict-free LDS, coalesced stores.
    float* gout = out + (size_t)b * 1296;
#pragma unroll
    for (int base = 0; base < 144; base += THREADS) {
        const int v = tid + base;
        if (v < 144) {
            const int qg  = v / 36;          // 0..3
            const int u   = qg >> 1;         // e1 group
            const int h   = qg & 1;          // e2 group
            const int e34 = v - qg * 36;

            const float* tb = &s_t[(u * 24 + h * 3) * 48 + e34];

            float r[3][5];
#pragma unroll
            for (int jj = 0; jj < 5; jj++) {
                r[0][jj] = tb[(0 * 8 + jj) * 48];
                r[1][jj] = tb[(1 * 8 + jj) * 48];
            }

#pragma unroll
            for (int e1l = 0; e1l < 3; e1l++) {
#pragma unroll
                for (int jj = 0; jj < 5; jj++)
                    r[(e1l + 2) % 3][jj] = tb[((e1l + 2) * 8 + jj) * 48];

                float acc[3];
#pragma unroll
                for (int e2 = 0; e2 < 3; e2++) acc[e2] = 0.0f;
#pragma unroll
                for (int i = 0; i < 3; i++) {
                    const float* row = r[(e1l + i) % 3];
#pragma unroll
                    for (int jj = 0; jj < 3; jj++) {
                        const float kv = k[i * 3 + jj];
#pragma unroll
                        for (int e2 = 0; e2 < 3; e2++)
                            acc[e2] = fmaf(row[e2 + jj], kv, acc[e2]);
                    }
                }

                const int e1 = u * 3 + e1l;
#pragma unroll
                for (int e2 = 0; e2 < 3; e2++)
                    gout[e1 * 216 + (h * 3 + e2) * 36 + e34] = acc[e2];
            }
        }
    }
}

extern "C" void kernel_launch(void* const* d_in, const int* in_sizes, int n_in,
                              void* d_out, int out_size)
{
    const float* in  = (const float*)d_in[0];   // (8192,8,8,8,8) fp32
    const float* ker = (const float*)d_in[1];   // (3,3) fp32
    float*       out = (float*)d_out;           // (8192,6,6,6,6) fp32

    const int batches = in_sizes[0] / 4096;     // 8192
    conv4d_shfl_kernel<<<batches, THREADS>>>(in, ker, out);
}

// round 10
// speedup vs baseline: 1.7500x; 1.0009x over previous
#include <cuda_runtime.h>
#include <cstdint>

// Conv4D with separable rank-1 kernel (K ⊗ K), VALID padding.
// input  : (8192, 8, 8, 8, 8) fp32 -> output (8192, 6, 6, 6, 6) fp32
//
// Pass 1 computed straight from coalesced LDG.128 registers using warp
// shuffles (no input staging in smem):
//   lane L, warp w, instr j  ->  plane 16w+2j+(L>>4), row (L>>1)&7, colhalf L&1
//   d4 conv: 1 shfl.bfly(1) borrow -> 5-col window -> rp[3][3]
//   d3 conv: rows rr+1, rr+2 via shfl.down 2 / 4
// T stored in smem with plane stride 48 (== 16 mod 32): store banks
// 16*hi + 6*rr + 3c all distinct -> conflict-free; pass-2 reads lanes along
// e34 (stride 1) -> conflict-free; coalesced output stores.

#define THREADS 128
#define FULLM 0xffffffffu

__global__ __launch_bounds__(THREADS, 8)
void conv4d_shfl_kernel(const float* __restrict__ in,
                        const float* __restrict__ ker,
                        float* __restrict__ out)
{
    __shared__ float s_t[64 * 48];   // T[plane][e34], stride 48: 12,288 B

    const int b   = blockIdx.x;
    const int tid = threadIdx.x;
    const int w   = tid >> 5;        // warp 0..3
    const int L   = tid & 31;        // lane

    const int hi = L >> 4;           // plane parity within pair
    const int rr = (L >> 1) & 7;     // input row 0..7
    const int c  = L & 1;            // col half 0..1

    float k[9];
#pragma unroll
    for (int i = 0; i < 9; i++) k[i] = __ldg(&ker[i]);

    const float4* gin4 = reinterpret_cast<const float4*>(in + (size_t)b * 4096);

    // ---- 8 fully-coalesced LDG.128 (4 lines per warp-op, MLP=8) ----
    float4 q[8];
#pragma unroll
    for (int j = 0; j < 8; j++)
        q[j] = __ldg(gin4 + w * 256 + j * 32 + L);

    const int plane_base = w * 16 + hi;          // plane = plane_base + 2j

    // ---- Pass 1: per plane j, conv (d3,d4) via shuffles ----
#pragma unroll
    for (int j = 0; j < 8; j++) {
        const float x0 = q[j].x, x1 = q[j].y, x2 = q[j].z, x3 = q[j].w;

        // borrow 1 float from the other col-half (col 4 for c=0, col 3 for c=1)
        const float sendv = c ? x0 : x3;
        const float recv  = __shfl_xor_sync(FULLM, sendv, 1);

        // 5-col window: cols 3c .. 3c+4
        float win[5];
        win[0] = c ? recv : x0;
        win[1] = c ? x0   : x1;
        win[2] = c ? x1   : x2;
        win[3] = c ? x2   : x3;
        win[4] = c ? x3   : recv;

        // row partials rp[kk][m]: e4 = 3c+m, kernel row kk
        float rp[3][3];
#pragma unroll
        for (int kk = 0; kk < 3; kk++)
#pragma unroll
            for (int m = 0; m < 3; m++)
                rp[kk][m] = fmaf(win[m],     k[kk * 3 + 0],
                            fmaf(win[m + 1], k[kk * 3 + 1],
                                 win[m + 2] * k[kk * 3 + 2]));

        // rows rr+1 (lane +2) and rr+2 (lane +4)
        float r1[3], r2[3];
#pragma unroll
        for (int m = 0; m < 3; m++) r1[m] = __shfl_down_sync(FULLM, rp[1][m], 2);
#pragma unroll
        for (int m = 0; m < 3; m++) r2[m] = __shfl_down_sync(FULLM, rp[2][m], 4);

        if (rr < 6) {
            const int plane = plane_base + 2 * j;
            float* tp = &s_t[plane * 48 + rr * 6 + c * 3];
            tp[0] = rp[0][0] + r1[0] + r2[0];
            tp[1] = rp[0][1] + r1[1] + r2[1];
            tp[2] = rp[0][2] + r1[2] + r2[2];
        }
    }
    __syncthreads();

    // ---- Pass 2: conv over (d1,d2). 144 units (u, h, e34), 5x5 rolling
    // window; lanes along e34 -> conflict-free LDS, coalesced stores.
    float* gout = out + (size_t)b * 1296;
#pragma unroll
    for (int base = 0; base < 144; base += THREADS) {
        const int v = tid + base;
        if (v < 144) {
            const int qg  = v / 36;          // 0..3
            const int u   = qg >> 1;         // e1 group
            const int h   = qg & 1;          // e2 group
            const int e34 = v - qg * 36;

            const float* tb = &s_t[(u * 24 + h * 3) * 48 + e34];

            float r[3][5];
#pragma unroll
            for (int jj = 0; jj < 5; jj++) {
                r[0][jj] = tb[(0 * 8 + jj) * 48];
                r[1][jj] = tb[(1 * 8 + jj) * 48];
            }

#pragma unroll
            for (int e1l = 0; e1l < 3; e1l++) {
#pragma unroll
                for (int jj = 0; jj < 5; jj++)
                    r[(e1l + 2) % 3][jj] = tb[((e1l + 2) * 8 + jj) * 48];

                float acc[3];
#pragma unroll
                for (int e2 = 0; e2 < 3; e2++) acc[e2] = 0.0f;
#pragma unroll
                for (int i = 0; i < 3; i++) {
                    const float* row = r[(e1l + i) % 3];
#pragma unroll
                    for (int jj = 0; jj < 3; jj++) {
                        const float kv = k[i * 3 + jj];
#pragma unroll
                        for (int e2 = 0; e2 < 3; e2++)
                            acc[e2] = fmaf(row[e2 + jj], kv, acc[e2]);
                    }
                }

                const int e1 = u * 3 + e1l;
#pragma unroll
                for (int e2 = 0; e2 < 3; e2++)
                    gout[e1 * 216 + (h * 3 + e2) * 36 + e34] = acc[e2];
            }
        }
    }
}

extern "C" void kernel_launch(void* const* d_in, const int* in_sizes, int n_in,
                              void* d_out, int out_size)
{
    const float* in  = (const float*)d_in[0];   // (8192,8,8,8,8) fp32
    const float* ker = (const float*)d_in[1];   // (3,3) fp32
    float*       out = (float*)d_out;           // (8192,6,6,6,6) fp32

    const int batches = in_sizes[0] / 4096;     // 8192
    conv4d_shfl_kernel<<<batches, THREADS>>>(in, ker, out);
}